// round 11
// baseline (speedup 1.0000x reference)
#include <cuda_runtime.h>
#include <cstdint>

// ---------------------------------------------------------------------------
// ClockworkGRU:
//   Phase A: clockwork-sparse projections (47% of dense GEMM).
//   Phase B: scan — 4-CTA cluster per SINGLE batch row, 256 threads/CTA,
//            71 KB SMEM  ->  2 co-resident clusters per SM. While one
//            cluster waits at its barrier/DSMEM exchange, the other issues.
// ---------------------------------------------------------------------------

#define GM 32768
#define GK 512
#define GN 512
#define SEQ_LEN 512
#define NBATCH 64

__device__ float g_proj[3ull * GM * GN];

__constant__ int c_SR[4]  = {8, 4, 6, 8};
__constant__ int c_SZ[4]  = {8, 4, 6, 8};
__constant__ int c_SH[4]  = {8, 4, 6, 8};
__constant__ int c_RPB[4] = {0, 256, 512, 1088};
__constant__ int c_ZPB[4] = {0, 256, 384, 576};
__constant__ int c_HPB[4] = {0, 256, 384, 576};
__constant__ int c_OFF[4] = {0, 128, 384, 768};

// ---------------- helpers ----------------------------------------------------
__device__ __forceinline__ unsigned long long pack2(float x, float y) {
    unsigned long long r;
    asm("mov.b64 %0, {%1, %2};" : "=l"(r) : "f"(x), "f"(y));
    return r;
}
__device__ __forceinline__ void fma2(unsigned long long& d,
                                     unsigned long long a,
                                     unsigned long long b) {
    asm("fma.rn.f32x2 %0, %1, %2, %0;" : "+l"(d) : "l"(a), "l"(b));
}
__device__ __forceinline__ float2 unpack2(unsigned long long v) {
    float2 r;
    asm("mov.b64 {%0, %1}, %2;" : "=f"(r.x), "=f"(r.y) : "l"(v));
    return r;
}
__device__ __forceinline__ float sigmoidf_(float x) {
    return 1.0f / (1.0f + __expf(-x));
}
__device__ __forceinline__ uint32_t smem_u32(const void* p) {
    return (uint32_t)__cvta_generic_to_shared(p);
}
__device__ __forceinline__ uint32_t mapa_u32(uint32_t addr, uint32_t rank) {
    uint32_t r;
    asm("mapa.shared::cluster.u32 %0, %1, %2;" : "=r"(r) : "r"(addr), "r"(rank));
    return r;
}
__device__ __forceinline__ void st_cluster_b64(uint32_t a, float x, float y) {
    unsigned long long v = pack2(x, y);
    asm volatile("st.shared::cluster.b64 [%0], %1;" :: "r"(a), "l"(v) : "memory");
}
#define CLUSTER_SYNC() do {                                           \
    asm volatile("barrier.cluster.arrive.aligned;" ::: "memory");     \
    asm volatile("barrier.cluster.wait.aligned;"   ::: "memory");     \
} while (0)

// ---------------------------------------------------------------------------
// Clockwork-sparse GEMM (unchanged from R10 — measured ~0.43 ms)
// ---------------------------------------------------------------------------
#define BM 128
#define BN 128
#define BKK 8

__global__ void __launch_bounds__(256) gemm3_kernel(
    const float* __restrict__ A,
    const float* __restrict__ W0, const float* __restrict__ b0,
    const float* __restrict__ W1, const float* __restrict__ b1,
    const float* __restrict__ W2, const float* __restrict__ b2)
{
    __shared__ float As[BKK][BM];
    __shared__ float Bs[BKK][BN];

    const int zi = blockIdx.z;
    const int z  = zi >> 2;
    const int cb = zi & 3;
    const int rpb_log = 9 - cb;
    const int ntiles = (NBATCH << rpb_log) >> 7;
    if ((int)blockIdx.y >= ntiles) return;

    const float* W    = (z == 0) ? W0 : (z == 1 ? W1 : W2);
    const float* bias = (z == 0) ? b0 : (z == 1 ? b1 : b2);
    float* C = g_proj + (size_t)z * GM * GN;

    const int m0 = blockIdx.y * BM;
    const int n0 = cb * 128;
    const int tid = threadIdx.x;

    const int a_row = tid >> 1;
    const int a_k   = (tid & 1) * 4;
    const int b_row = tid >> 5;
    const int b_col = (tid & 31) * 4;

    const int warp = tid >> 5;
    const int lane = tid & 31;
    const int row0 = (warp & 3) * 32 + (lane & 3) * 8;
    const int col0 = (warp >> 2) * 64 + (lane >> 2) * 8;

    const int rpb_mask = (1 << rpb_log) - 1;
    const int gA = m0 + a_row;
    const int arow_act = ((gA >> rpb_log) << 9) + ((gA & rpb_mask) << cb);

    unsigned long long acc[8][4];
#pragma unroll
    for (int i = 0; i < 8; i++)
#pragma unroll
        for (int j = 0; j < 4; j++) acc[i][j] = 0ull;

    const float* Aptr = A + (size_t)arow_act * GK + a_k;
    const float* Wptr = W + (size_t)b_row * GN + n0 + b_col;

    float4 ra = *(const float4*)Aptr;
    float4 rb = *(const float4*)Wptr;

    const int KT = GK / BKK;
    for (int kt = 0; kt < KT; kt++) {
        As[a_k + 0][a_row] = ra.x;
        As[a_k + 1][a_row] = ra.y;
        As[a_k + 2][a_row] = ra.z;
        As[a_k + 3][a_row] = ra.w;
        *(float4*)&Bs[b_row][b_col] = rb;
        __syncthreads();

        if (kt + 1 < KT) {
            ra = *(const float4*)(Aptr + (kt + 1) * BKK);
            rb = *(const float4*)(Wptr + (size_t)(kt + 1) * BKK * GN);
        }

#pragma unroll
        for (int k = 0; k < BKK; k++) {
            float4 a0 = *(const float4*)&As[k][row0];
            float4 a1 = *(const float4*)&As[k][row0 + 4];
            ulonglong2 bq0 = *(const ulonglong2*)&Bs[k][col0];
            ulonglong2 bq1 = *(const ulonglong2*)&Bs[k][col0 + 4];
            unsigned long long av[8];
            av[0] = pack2(a0.x, a0.x); av[1] = pack2(a0.y, a0.y);
            av[2] = pack2(a0.z, a0.z); av[3] = pack2(a0.w, a0.w);
            av[4] = pack2(a1.x, a1.x); av[5] = pack2(a1.y, a1.y);
            av[6] = pack2(a1.z, a1.z); av[7] = pack2(a1.w, a1.w);
#pragma unroll
            for (int i = 0; i < 8; i++) {
                fma2(acc[i][0], av[i], bq0.x);
                fma2(acc[i][1], av[i], bq0.y);
                fma2(acc[i][2], av[i], bq1.x);
                fma2(acc[i][3], av[i], bq1.y);
            }
        }
        __syncthreads();
    }

    float bb[8];
#pragma unroll
    for (int j = 0; j < 8; j++) bb[j] = bias[n0 + col0 + j];

#pragma unroll
    for (int i = 0; i < 8; i++) {
        float o[8];
#pragma unroll
        for (int jp = 0; jp < 4; jp++) {
            float2 v = unpack2(acc[i][jp]);
            o[2 * jp]     = v.x + bb[2 * jp];
            o[2 * jp + 1] = v.y + bb[2 * jp + 1];
        }
        const int g2 = m0 + row0 + i;
        const int crow = ((g2 >> rpb_log) << 9) + ((g2 & rpb_mask) << cb);
        size_t base = (size_t)crow * GN + n0 + col0;
        *(float4*)&C[base]     = make_float4(o[0], o[1], o[2], o[3]);
        *(float4*)&C[base + 4] = make_float4(o[4], o[5], o[6], o[7]);
    }
}

// ---------------------------------------------------------------------------
// single-row warp-coalesced dots
// ---------------------------------------------------------------------------

// WIDE lanes own 4 consecutive cols per k-row; 64 rows, 8+8 double-buffered.
template<int WIDE>  // 32 or 24
__device__ __forceinline__ void wdot_wide(const float* __restrict__ Wp, int stride,
                                          const float* __restrict__ h,
                                          float* a, int lane)
{
    const float* p = Wp + lane * 4;
    float4 A[8], B[8];
#pragma unroll
    for (int r = 0; r < 8; r++) A[r] = *(const float4*)(p + (size_t)r * stride);
#pragma unroll
    for (int kb = 0; kb < 64; kb += 16) {
#pragma unroll
        for (int r = 0; r < 8; r++)
            B[r] = *(const float4*)(p + (size_t)(kb + 8 + r) * stride);
#pragma unroll
        for (int r = 0; r < 8; r++) {
            float x = h[kb + r];
            a[0] = fmaf(x, A[r].x, a[0]); a[1] = fmaf(x, A[r].y, a[1]);
            a[2] = fmaf(x, A[r].z, a[2]); a[3] = fmaf(x, A[r].w, a[3]);
        }
        if (kb + 16 < 64) {
#pragma unroll
            for (int r = 0; r < 8; r++)
                A[r] = *(const float4*)(p + (size_t)(kb + 16 + r) * stride);
        }
#pragma unroll
        for (int r = 0; r < 8; r++) {
            float x = h[kb + 8 + r];
            a[0] = fmaf(x, B[r].x, a[0]); a[1] = fmaf(x, B[r].y, a[1]);
            a[2] = fmaf(x, B[r].z, a[2]); a[3] = fmaf(x, B[r].w, a[3]);
        }
    }
}

// 32-col slices, arbitrary row stride: 4 rows x 8 col-quads per warp-load,
// 64 rows total; all 16 loads prefetched; shfl reduce; lanes 0-7 hold sums.
__device__ __forceinline__ void wdot_w8s(const float* __restrict__ Wp, int stride,
                                         const float* __restrict__ h,
                                         float* a, int lane)
{
    const int sr = lane >> 3, sc = lane & 7;
    const float* p = Wp + sr * stride + sc * 4;
    float4 A[8], B[8];
#pragma unroll
    for (int i = 0; i < 8; i++)
        A[i] = *(const float4*)(p + (size_t)(i * 4) * stride);
#pragma unroll
    for (int i = 0; i < 8; i++)
        B[i] = *(const float4*)(p + (size_t)((i + 8) * 4) * stride);
#pragma unroll
    for (int i = 0; i < 8; i++) {
        float x = h[i * 4 + sr];
        a[0] = fmaf(x, A[i].x, a[0]); a[1] = fmaf(x, A[i].y, a[1]);
        a[2] = fmaf(x, A[i].z, a[2]); a[3] = fmaf(x, A[i].w, a[3]);
    }
#pragma unroll
    for (int i = 0; i < 8; i++) {
        float x = h[(i + 8) * 4 + sr];
        a[0] = fmaf(x, B[i].x, a[0]); a[1] = fmaf(x, B[i].y, a[1]);
        a[2] = fmaf(x, B[i].z, a[2]); a[3] = fmaf(x, B[i].w, a[3]);
    }
#pragma unroll
    for (int j = 0; j < 4; j++) {
        a[j] += __shfl_xor_sync(0xffffffffu, a[j], 8);
        a[j] += __shfl_xor_sync(0xffffffffu, a[j], 16);
    }
}

// smem dot, KSEG deep, stride STR, single row
template<int KSEG, int STR>
__device__ __forceinline__ void dot_s41(const float* __restrict__ w,
                                        const float* __restrict__ h, float* a)
{
#pragma unroll
    for (int k = 0; k < KSEG; k++) {
        float4 ww = *(const float4*)&w[k * STR];
        float x = h[k];
        a[0] = fmaf(x, ww.x, a[0]); a[1] = fmaf(x, ww.y, a[1]);
        a[2] = fmaf(x, ww.z, a[2]); a[3] = fmaf(x, ww.w, a[3]);
    }
}

__device__ __forceinline__ void fold4(float* a, const float4& b) {
    a[0] += b.x; a[1] += b.y; a[2] += b.z; a[3] += b.w;
}

// ---------------------------------------------------------------------------
__global__ void __launch_bounds__(256, 2) __cluster_dims__(4, 1, 1)
scan_kernel(
    const float* __restrict__ ch0, const float* __restrict__ cr0, const float* __restrict__ cz0,
    const float* __restrict__ ch1, const float* __restrict__ cr1, const float* __restrict__ cz1,
    const float* __restrict__ ch2, const float* __restrict__ cr2, const float* __restrict__ cz2,
    const float* __restrict__ ch3, const float* __restrict__ cr3, const float* __restrict__ cz3,
    float* __restrict__ out)
{
    extern __shared__ float smem[];
    float* h_s   = smem;              // 512
    float* rh_s  = smem + 512;        // 1280
    float* rp    = smem + 1792;       // 2112 r partials
    float* zp    = smem + 3904;       // 832 z partials
    float* hp    = smem + 4736;       // 832 hn partials
    float* cr0_s = smem + 5568;       // 128 x 32
    float* cz0_s = smem + 9664;       // 128 x 32
    float* ch0_s = smem + 13760;      // 128 x 32  (end 17856 floats = 71424 B)

    const int rank = blockIdx.x & 3;
    const int b    = blockIdx.x >> 2;
    const int tid  = threadIdx.x;
    const int wid  = tid >> 5;
    const int lane = tid & 31;

    // preload own-column slice of block-0 matrices (48 KB)
    for (int i = tid; i < 1024; i += 256) {
        const int row = i >> 3, c4 = (i & 7) * 4;
        const int src = row * 128 + rank * 32 + c4;
        const int dst = row * 32 + c4;
        *(float4*)&cr0_s[dst] = *(const float4*)&cr0[src];
        *(float4*)&cz0_s[dst] = *(const float4*)&cz0[src];
        *(float4*)&ch0_s[dst] = *(const float4*)&ch0[src];
    }
    h_s[tid] = 0.0f; h_s[256 + tid] = 0.0f;
    __syncthreads();
    CLUSTER_SYNC();

    uint32_t peer_rh[3], peer_h[3];
    {
        int p = 0;
        for (int r = 0; r < 4; r++) {
            if (r == rank) continue;
            peer_rh[p] = mapa_u32(smem_u32(rh_s), (uint32_t)r);
            peer_h[p]  = mapa_u32(smem_u32(h_s),  (uint32_t)r);
            p++;
        }
    }

    const float* xt  = g_proj;
    const float* xrt = g_proj + (size_t)GM * GN;
    const float* xzt = g_proj + 2ull * GM * GN;

    for (int t = 0; t < SEQ_LEN; t++) {
        const bool aa1 = (t & 1) == 0, aa2 = (t & 3) == 0, aa3 = (t & 7) == 0;
        int act[4]; int na = 0;
        act[na++] = 0;
        if (aa1) act[na++] = 1;
        if (aa2) act[na++] = 2;
        if (aa3) act[na++] = 3;

        const size_t xr0 = ((size_t)b * SEQ_LEN + t) * GN;

        // ============ pass 1: r/z dots → private partial slots ==============
        // warp tasks: streamed blocks 1,2,3
        {
            const int nwt = (aa1 ? 12 : 0) + (aa2 ? 12 : 0) + (aa3 ? 16 : 0);
            for (int wt = wid; wt < nwt; wt += 8) {
                int k = wt;
                float A[4] = {0,0,0,0};
                if (aa1) {
                    if (k < 8) {                          // block1 r (64 own cols)
                        const int seg = k >> 1, g = k & 1;
                        wdot_w8s(cr1 + (size_t)(seg * 64) * 256
                                     + rank * 64 + g * 32, 256,
                                 h_s + seg * 64, A, lane);
                        if (lane < 8) {
                            const int c = g * 32 + lane * 4;
                            if (seg == 0)
                                fold4(A, *(const float4*)&xrt[xr0 + rank * 64 + c]);
                            *(float4*)(rp + 256 + seg * 64 + c) =
                                make_float4(A[0], A[1], A[2], A[3]);
                        }
                        continue;
                    }
                    k -= 8;
                    if (k < 4) {                          // block1 z
                        const int seg = k;
                        wdot_w8s(cz1 + (size_t)(seg * 64) * 128 + rank * 32, 128,
                                 h_s + seg * 64, A, lane);
                        if (lane < 8) {
                            if (seg == 0)
                                fold4(A, *(const float4*)&xzt[xr0 + 128 + rank * 32 + lane * 4]);
                            *(float4*)(zp + 256 + seg * 32 + lane * 4) =
                                make_float4(A[0], A[1], A[2], A[3]);
                        }
                        continue;
                    }
                    k -= 4;
                }
                if (aa2) {
                    if (k < 6) {                          // block2 r (96 own cols)
                        const int seg = k;
                        if (lane < 24) {
                            wdot_wide<24>(cr2 + (size_t)(seg * 64) * 384 + rank * 96,
                                          384, h_s + seg * 64, A, lane);
                            if (seg == 0)
                                fold4(A, *(const float4*)&xrt[xr0 + rank * 96 + lane * 4]);
                            *(float4*)(rp + 512 + seg * 96 + lane * 4) =
                                make_float4(A[0], A[1], A[2], A[3]);
                        }
                        continue;
                    }
                    k -= 6;
                    if (k < 6) {                          // block2 z
                        const int seg = k;
                        wdot_w8s(cz2 + (size_t)(seg * 64) * 128 + rank * 32, 128,
                                 h_s + seg * 64, A, lane);
                        if (lane < 8) {
                            if (seg == 0)
                                fold4(A, *(const float4*)&xzt[xr0 + 256 + rank * 32 + lane * 4]);
                            *(float4*)(zp + 384 + seg * 32 + lane * 4) =
                                make_float4(A[0], A[1], A[2], A[3]);
                        }
                        continue;
                    }
                    k -= 6;
                }
                if (k < 8) {                              // block3 r (128 own cols)
                    const int seg = k;
                    wdot_wide<32>(cr3 + (size_t)(seg * 64) * 512 + rank * 128,
                                  512, h_s + seg * 64, A, lane);
                    if (seg == 0)
                        fold4(A, *(const float4*)&xrt[xr0 + rank * 128 + lane * 4]);
                    *(float4*)(rp + 1088 + seg * 128 + lane * 4) =
                        make_float4(A[0], A[1], A[2], A[3]);
                } else {                                  // block3 z
                    const int seg = k - 8;
                    wdot_w8s(cz3 + (size_t)(seg * 64) * 128 + rank * 32, 128,
                             h_s + seg * 64, A, lane);
                    if (lane < 8) {
                        if (seg == 0)
                            fold4(A, *(const float4*)&xzt[xr0 + 384 + rank * 32 + lane * 4]);
                        *(float4*)(zp + 576 + seg * 32 + lane * 4) =
                            make_float4(A[0], A[1], A[2], A[3]);
                    }
                }
            }
        }
        // thread tasks: SMEM block 0 (64 r + 64 z, 16-deep)
        if (tid < 128) {
            int tk = tid;
            float A[4] = {0,0,0,0};
            if (tk < 64) {                                // b0 r
                const int q = tk & 7, seg = tk >> 3, c = q * 4;
                dot_s41<16, 32>(cr0_s + seg * 512 + c, h_s + seg * 16, A);
                if (seg == 0)
                    fold4(A, *(const float4*)&xrt[xr0 + rank * 32 + c]);
                *(float4*)(rp + seg * 32 + c) = make_float4(A[0], A[1], A[2], A[3]);
            } else {                                      // b0 z
                tk -= 64;
                const int q = tk & 7, seg = tk >> 3, c = q * 4;
                dot_s41<16, 32>(cz0_s + seg * 512 + c, h_s + seg * 16, A);
                if (seg == 0)
                    fold4(A, *(const float4*)&xzt[xr0 + rank * 32 + c]);
                *(float4*)(zp + seg * 32 + c) = make_float4(A[0], A[1], A[2], A[3]);
            }
        }
        __syncthreads();

        // ============ pass 2: reduce r, rh = sig(r)*h, exchange =============
        {
            int pcount[4]; int npairs = 0;
            for (int a = 0; a < na; a++) {
                pcount[a] = (act[a] + 1) * 16;
                npairs += pcount[a];
            }
            for (int s = tid; s < npairs; s += 256) {
                int p = s;
                int i = 0;
                for (int a = 0; a < na; a++) {
                    if (p < pcount[a]) { i = act[a]; break; }
                    p -= pcount[a];
                }
                const int colsP = (i + 1) * 32;
                const int c2 = p * 2;
                const int j = rank * colsP + c2;
                const float* P = rp + c_RPB[i] + c2;
                float s0 = 0.f, s1 = 0.f;
                const int ns = c_SR[i];
                for (int sg = 0; sg < ns; sg++) {
                    s0 += P[sg * colsP];
                    s1 += P[sg * colsP + 1];
                }
                const float v0 = sigmoidf_(s0) * h_s[j];
                const float v1 = sigmoidf_(s1) * h_s[j + 1];
                const int idx = c_OFF[i] + j;
                rh_s[idx]     = v0;
                rh_s[idx + 1] = v1;
                const uint32_t off = (uint32_t)idx * 4u;
                st_cluster_b64(peer_rh[0] + off, v0, v1);
                st_cluster_b64(peer_rh[1] + off, v0, v1);
                st_cluster_b64(peer_rh[2] + off, v0, v1);
            }
        }
        CLUSTER_SYNC();

        // ============ pass 3: hn-dots → private partials ====================
        {
            const int nwh = (aa1 ? 4 : 0) + (aa2 ? 6 : 0) + (aa3 ? 8 : 0);
            for (int wt = wid; wt < nwh; wt += 8) {
                int k = wt;
                float A[4] = {0,0,0,0};
                int i, seg;
                const float* base;
                if (aa1 && k < 4)      { i = 1; seg = k; base = ch1; }
                else {
                    if (aa1) k -= 4;
                    if (aa2 && k < 6)  { i = 2; seg = k; base = ch2; }
                    else { if (aa2) k -= 6; i = 3; seg = k; base = ch3; }
                }
                wdot_w8s(base + (size_t)(seg * 64) * 128 + rank * 32, 128,
                         rh_s + c_OFF[i] + seg * 64, A, lane);
                if (lane < 8) {
                    if (seg == 0)
                        fold4(A, *(const float4*)&xt[xr0 + (i << 7) + rank * 32 + lane * 4]);
                    *(float4*)(hp + c_HPB[i] + seg * 32 + lane * 4) =
                        make_float4(A[0], A[1], A[2], A[3]);
                }
            }
        }
        if (tid < 64) {                                   // b0 hn
            const int q = tid & 7, seg = tid >> 3, c = q * 4;
            float A[4] = {0,0,0,0};
            dot_s41<16, 32>(ch0_s + seg * 512 + c, rh_s + seg * 16, A);
            if (seg == 0)
                fold4(A, *(const float4*)&xt[xr0 + rank * 32 + c]);
            *(float4*)(hp + seg * 32 + c) = make_float4(A[0], A[1], A[2], A[3]);
        }
        __syncthreads();

        // ============ pass 4: reduce z/hn, gate, update h, exchange =========
        {
            const int npairs = na * 16;
            if (tid < npairs) {
                const int i = act[tid >> 4];
                const int c2 = (tid & 15) * 2;
                const int lc = rank * 32 + c2;
                const int gc = (i << 7) + lc;
                const float* Pz = zp + c_ZPB[i] + c2;
                const float* Ph = hp + c_HPB[i] + c2;
                float z0 = 0.f, z1 = 0.f, n0 = 0.f, n1 = 0.f;
                const int nz = c_SZ[i];
                for (int sg = 0; sg < nz; sg++) {
                    z0 += Pz[sg * 32];
                    z1 += Pz[sg * 32 + 1];
                }
                const int nh = c_SH[i];
                for (int sg = 0; sg < nh; sg++) {
                    n0 += Ph[sg * 32];
                    n1 += Ph[sg * 32 + 1];
                }
                const float zz0 = sigmoidf_(z0), zz1 = sigmoidf_(z1);
                const float hn0 = sigmoidf_(n0), hn1 = sigmoidf_(n1);
                const float v0 = zz0 * hn0 + (1.0f - zz0) * h_s[gc];
                const float v1 = zz1 * hn1 + (1.0f - zz1) * h_s[gc + 1];
                h_s[gc] = v0; h_s[gc + 1] = v1;
                const uint32_t off = (uint32_t)gc * 4u;
                st_cluster_b64(peer_h[0] + off, v0, v1);
                st_cluster_b64(peer_h[1] + off, v0, v1);
                st_cluster_b64(peer_h[2] + off, v0, v1);
            }
        }
        __syncthreads();

        // output: own 128 cols
        if (tid < 128) {
            const int i = tid >> 5, c = tid & 31;
            const int gc = i * 128 + rank * 32 + c;
            out[xr0 + gc] = h_s[gc];
        }
        CLUSTER_SYNC();
    }
}

// ---------------------------------------------------------------------------
extern "C" void kernel_launch(void* const* d_in, const int* in_sizes, int n_in,
                              void* d_out, int out_size) {
    (void)in_sizes; (void)n_in; (void)out_size;
    const float* x  = (const float*)d_in[0];
    const float* W  = (const float*)d_in[1];
    const float* bb = (const float*)d_in[2];
    const float* Wr = (const float*)d_in[3];
    const float* br = (const float*)d_in[4];
    const float* Wz = (const float*)d_in[5];
    const float* bz = (const float*)d_in[6];
    const float* ch[4]; const float* cr[4]; const float* cz[4];
    for (int i = 0; i < 4; i++) {
        ch[i] = (const float*)d_in[7 + 3 * i + 0];
        cr[i] = (const float*)d_in[7 + 3 * i + 1];
        cz[i] = (const float*)d_in[7 + 3 * i + 2];
    }
    float* out = (float*)d_out;

    dim3 grid(1, 256, 12);
    gemm3_kernel<<<grid, 256>>>(x, W, bb, Wr, br, Wz, bz);

    size_t smem_bytes = 17856 * sizeof(float);   // 71,424 B -> 2 CTAs/SM
    cudaFuncSetAttribute(scan_kernel,
                         cudaFuncAttributeMaxDynamicSharedMemorySize,
                         (int)smem_bytes);
    scan_kernel<<<NBATCH * 4, 256, smem_bytes>>>(
        ch[0], cr[0], cz[0],
        ch[1], cr[1], cz[1],
        ch[2], cr[2], cz[2],
        ch[3], cr[3], cz[3],
        out);
}